// round 13
// baseline (speedup 1.0000x reference)
#include <cuda_runtime.h>
#include <cuda_fp16.h>
#include <cuda_bf16.h>
#include <cstdint>

// ---------------- problem constants ----------------
#define NB   64
#define NT   256
#define NC   256
#define HW   4096
#define NITER 30

#define K2C     28.853900817779268f   // log2(e)/eps
#define INV_K2  0.03465735902799727f  // eps*ln2
#define SHIFTF  26.0f
#define MUC     (1.0f/256.0f)

// ---------------- scratch ----------------
__device__ __align__(16) __nv_bfloat16 g_tok[(size_t)2 * NB * NT * NC];  // [z][b][i][c] RAW samples
__device__ __align__(16) float         g_pss[(size_t)2 * NB * NT * 8];   // [z][b][i][chunk] partial ss
__device__ __align__(16) __half        g_K[(size_t)NB * NT * NT];
__device__ float    g_part[2 * NB];
__device__ unsigned g_ctr;

__device__ __forceinline__ uint32_t smem_u32(const void* p) {
    uint32_t a;
    asm("{ .reg .u64 t; cvta.to.shared.u64 t, %1; cvt.u32.u64 %0, t; }" : "=r"(a) : "l"(p));
    return a;
}
__device__ __forceinline__ uint32_t h2_as_u32(__half lo, __half hi) {
    union { __half2 h; uint32_t u; } c;
    c.h = __halves2half2(lo, hi);
    return c.u;
}

// ============================================================================
// Kernel 1: slim streaming gather. grid (64, 2, 8) = 1024 CTAs, 256 threads.
// CTA = (batch, tensor, 32-channel chunk): streams 512KB coalesced, extracts
// linspace samples to smem, writes token-major bf16 slice + partial sumsq.
// Norms are applied later in the cost kernel epilogue (normalization commutes
// with the dot product).
// ============================================================================
#define GST 264   // smem stage row stride (bf16)

__global__ __launch_bounds__(256) void gather_kernel(
    const float* __restrict__ pred, const float* __restrict__ tgt)
{
    __shared__ __nv_bfloat16 stage[32 * GST];

    const int b = blockIdx.x, z = blockIdx.y, chunk = blockIdx.z;
    if (threadIdx.x == 0 && (b | z | chunk) == 0) g_ctr = 0u;

    const int tid = threadIdx.x;
    const float DELTA = 4095.0f / 255.0f;

    // per-thread window hits (channel-independent): windows tid + k*256
    int hit_i[4], hit_off[4];
    #pragma unroll
    for (int k = 0; k < 4; ++k) {
        const int p4 = (tid + k * 256) * 4;
        const int cand = (int)(__fdividef((float)(p4 + 2), DELTA));
        hit_i[k] = -1; hit_off[k] = 0;
        #pragma unroll
        for (int d = -1; d <= 1; ++d) {
            const int i = cand + d;
            if (i >= 0 && i < 256) {
                const int s = (int)(__fmul_rn((float)i, DELTA));  // exact ref trunc
                if (s >= p4 && s < p4 + 4) { hit_i[k] = i; hit_off[k] = s - p4; }
            }
        }
    }

    const float4* __restrict__ src =
        (const float4*)((z ? tgt : pred) + ((size_t)b * NC + chunk * 32) * HW);

    #pragma unroll 4
    for (int cc = 0; cc < 32; ++cc) {
        float4 f[4];
        #pragma unroll
        for (int k = 0; k < 4; ++k) f[k] = __ldcs(&src[(size_t)cc * 1024 + tid + k * 256]);
        #pragma unroll
        for (int k = 0; k < 4; ++k) {
            if (hit_i[k] >= 0) {
                const float* fv = (const float*)&f[k];
                stage[cc * GST + hit_i[k]] = __float2bfloat16(fv[hit_off[k]]);
            }
        }
    }
    __syncthreads();

    // partial sum of squares for token tid over this CTA's 32 channels
    {
        float ss = 0.0f;
        #pragma unroll 8
        for (int cc = 0; cc < 32; ++cc) {
            const float x = __bfloat162float(stage[cc * GST + tid]);
            ss = fmaf(x, x, ss);
        }
        g_pss[(((size_t)z * NB + b) * NT + tid) * 8 + chunk] = ss;
    }

    // coalesced token-major write: token i gets 32 ch = 64B (4x uint4)
    __nv_bfloat16* __restrict__ dst =
        g_tok + ((size_t)z * NB + b) * NT * NC + chunk * 32;
    const int part = tid & 3;         // 8-channel group
    #pragma unroll
    for (int it = 0; it < 4; ++it) {
        const int i = (tid >> 2) + it * 64;
        union { uint4 u; __nv_bfloat16 h[8]; } o;
        #pragma unroll
        for (int j = 0; j < 8; ++j)
            o.h[j] = stage[(part * 8 + j) * GST + i];
        *(uint4*)(dst + (size_t)i * NC + part * 8) = o.u;
    }
}

// ============================================================================
// Kernel 2: cost GEMM via mma.sync bf16 on RAW tokens; norms applied in the
// epilogue: dotn = dot * invp[m] * invt[n];  K' = exp2((dotn-1)*K2C + 26).
// ============================================================================
#define SPAD 264
#define COST_SMEM ((128 + 256) * SPAD * 2 + (128 + 256) * 4)

__device__ __forceinline__ void mma16816bf(float* c, uint32_t a0, uint32_t a1,
                                           uint32_t a2, uint32_t a3,
                                           uint32_t b0, uint32_t b1) {
    asm volatile(
        "mma.sync.aligned.m16n8k16.row.col.f32.bf16.bf16.f32 "
        "{%0,%1,%2,%3}, {%4,%5,%6,%7}, {%8,%9}, {%0,%1,%2,%3};"
        : "+f"(c[0]), "+f"(c[1]), "+f"(c[2]), "+f"(c[3])
        : "r"(a0), "r"(a1), "r"(a2), "r"(a3), "r"(b0), "r"(b1));
}

__global__ __launch_bounds__(256, 1) void cost_kernel()
{
    extern __shared__ char smem[];
    __nv_bfloat16* As = (__nv_bfloat16*)smem;
    __nv_bfloat16* Bs = (__nv_bfloat16*)(smem + 128 * SPAD * 2);
    float* invp = (float*)(smem + (128 + 256) * SPAD * 2);   // [128]
    float* invt = invp + 128;                                 // [256]

    const int mh = blockIdx.x;
    const int b  = blockIdx.y;
    const int tid = threadIdx.x, w = tid >> 5, lane = tid & 31;

    // ---- inverse norms from g_pss partials
    if (tid < 128) {
        const float* ps = g_pss + (((size_t)0 * NB + b) * NT + mh * 128 + tid) * 8;
        const float ss = ((ps[0] + ps[1]) + (ps[2] + ps[3]))
                       + ((ps[4] + ps[5]) + (ps[6] + ps[7]));
        invp[tid] = __fdividef(1.0f, fmaxf(sqrtf(ss), 1e-12f));
    }
    {
        const float* ps = g_pss + (((size_t)NB + b) * NT + tid) * 8;
        const float ss = ((ps[0] + ps[1]) + (ps[2] + ps[3]))
                       + ((ps[4] + ps[5]) + (ps[6] + ps[7]));
        invt[tid] = __fdividef(1.0f, fmaxf(sqrtf(ss), 1e-12f));
    }

    const uint4* __restrict__ Ag =
        (const uint4*)(g_tok + ((size_t)b * NT + (size_t)mh * 128) * NC);
    #pragma unroll
    for (int it = 0; it < 16; ++it) {
        const int idx = tid + it * 256;
        *(uint4*)(As + (idx >> 5) * SPAD + (idx & 31) * 8) = Ag[idx];
    }
    const uint4* __restrict__ Bg = (const uint4*)(g_tok + ((size_t)(NB + b)) * NT * NC);
    #pragma unroll
    for (int it = 0; it < 32; ++it) {
        const int idx = tid + it * 256;
        *(uint4*)(Bs + (idx >> 5) * SPAD + (idx & 31) * 8) = Bg[idx];
    }
    __syncthreads();

    const int r0 = w * 16;
    const int lr = lane >> 2;
    const int lj = lane & 3;

    const __nv_bfloat16* A0 = As + (r0 + lr) * SPAD + lj * 2;
    const __nv_bfloat16* A8 = A0 + 8 * SPAD;
    const __nv_bfloat16* B0 = Bs + lr * SPAD + lj * 2;

    __half* __restrict__ K0 = g_K + ((size_t)b * NT + (size_t)(mh * 128 + r0 + lr)) * NT;
    __half* __restrict__ K8 = K0 + 8 * NT;
    const float ip0 = invp[r0 + lr];
    const float ip8 = invp[r0 + 8 + lr];

    #pragma unroll
    for (int h = 0; h < 2; ++h) {
        float c[16][4];
        #pragma unroll
        for (int nt = 0; nt < 16; ++nt)
            c[nt][0] = c[nt][1] = c[nt][2] = c[nt][3] = 0.0f;

        #pragma unroll
        for (int kc = 0; kc < 16; ++kc) {
            const int ko = kc * 16;
            const uint32_t a0 = *(const uint32_t*)(A0 + ko);
            const uint32_t a1 = *(const uint32_t*)(A8 + ko);
            const uint32_t a2 = *(const uint32_t*)(A0 + ko + 8);
            const uint32_t a3 = *(const uint32_t*)(A8 + ko + 8);
            #pragma unroll
            for (int nt = 0; nt < 16; ++nt) {
                const __nv_bfloat16* bp = B0 + (h * 128 + nt * 8) * SPAD + ko;
                mma16816bf(c[nt], a0, a1, a2, a3,
                           *(const uint32_t*)bp, *(const uint32_t*)(bp + 8));
            }
        }

        #pragma unroll
        for (int nt = 0; nt < 16; ++nt) {
            const int col = h * 128 + nt * 8 + lj * 2;
            const float it0 = invt[col], it1 = invt[col + 1];
            const float d00 = c[nt][0] * ip0 * it0, d01 = c[nt][1] * ip0 * it1;
            const float d80 = c[nt][2] * ip8 * it0, d81 = c[nt][3] * ip8 * it1;
            *(__half2*)(K0 + col) = __halves2half2(
                __float2half_rn(exp2f(fmaf(d00 - 1.0f, K2C, SHIFTF))),
                __float2half_rn(exp2f(fmaf(d01 - 1.0f, K2C, SHIFTF))));
            *(__half2*)(K8 + col) = __halves2half2(
                __float2half_rn(exp2f(fmaf(d80 - 1.0f, K2C, SHIFTF))),
                __float2half_rn(exp2f(fmaf(d81 - 1.0f, K2C, SHIFTF))));
        }
    }
}

// ============================================================================
// Kernel 3: Sinkhorn, WARP-SPECIALIZED (unchanged from round 12).
// ============================================================================
#define SK_KS    0
#define SK_RECV  65536                 // [2][256] f32 peer-pushed colsums
#define SK_V     (SK_RECV + 2048)      // [256] f32
#define SK_U     (SK_V + 1024)         // [128] f32
#define SK_UH    (SK_U + 512)          // [128] f16 (scaled x64)
#define SK_VH    (SK_UH + 256)         // [256] f16
#define SK_RED   (SK_VH + 512)         // [16] f32 (pad)
#define SK_MBAR  (SK_RED + 128)
#define SK_SMEM  (SK_MBAR + 16)

__device__ __forceinline__ void mma16816f(float* c, uint32_t a0, uint32_t a1,
                                          uint32_t a2, uint32_t a3,
                                          uint32_t b0, uint32_t b1) {
    asm volatile(
        "mma.sync.aligned.m16n8k16.row.col.f32.f16.f16.f32 "
        "{%0,%1,%2,%3}, {%4,%5,%6,%7}, {%8,%9}, {%0,%1,%2,%3};"
        : "+f"(c[0]), "+f"(c[1]), "+f"(c[2]), "+f"(c[3])
        : "r"(a0), "r"(a1), "r"(a2), "r"(a3), "r"(b0), "r"(b1));
}

__global__ __launch_bounds__(512, 1) __cluster_dims__(2, 1, 1)
void sinkhorn_kernel(float* __restrict__ out)
{
    extern __shared__ unsigned char sm[];
    __half* Ks   = (__half*)(sm + SK_KS);      // [128][256] local rows
    float*  recv = (float*)(sm + SK_RECV);
    float*  v    = (float*)(sm + SK_V);
    float*  u    = (float*)(sm + SK_U);
    __half* uh   = (__half*)(sm + SK_UH);
    __half* vh   = (__half*)(sm + SK_VH);
    float*  red  = (float*)(sm + SK_RED);

    const int rank = blockIdx.x & 1;
    const int b    = blockIdx.x >> 1;
    const int tid  = threadIdx.x;
    const int w    = tid >> 5, lane = tid & 31;
    const int lr4  = lane >> 2, lj = lane & 3;

    const uint32_t mbar_local = smem_u32(sm + SK_MBAR);
    uint32_t recv_peer, mbar_peer;
    {
        const uint32_t recv_local = smem_u32(recv);
        asm("mapa.shared::cluster.u32 %0, %1, %2;" : "=r"(recv_peer)
            : "r"(recv_local), "r"(rank ^ 1));
        asm("mapa.shared::cluster.u32 %0, %1, %2;" : "=r"(mbar_peer)
            : "r"(mbar_local), "r"(rank ^ 1));
    }

    if (tid == 0) {
        asm volatile("mbarrier.init.shared.b64 [%0], %1;"
                     :: "r"(mbar_local), "r"(32u) : "memory");
    }

    {   // load my 128 rows of K' (64 KB)
        const uint4* gk = (const uint4*)(g_K + ((size_t)b * NT + (size_t)rank * 128) * NT);
        uint4* sk = (uint4*)Ks;
        #pragma unroll
        for (int q = 0; q < 8; ++q) sk[tid + q * 512] = gk[tid + q * 512];
    }
    if (tid < NT) { v[tid] = 1.0f; vh[tid] = __float2half_rn(1.0f); }
    __syncthreads();

    // cluster sync once: peer mbarrier init visible before any remote push
    asm volatile("barrier.cluster.arrive.aligned;" ::: "memory");
    asm volatile("barrier.cluster.wait.aligned;" ::: "memory");

    // ---- role-shared fragment storage (disjoint indexing per role) ----
    uint32_t frag[64];
    const bool roww = (w < 8);
    const int rt = w;           // row warp: rows rt*16..+15
    const int wc = w - 8;       // col warp: ntiles wc*4..wc*4+3

    if (roww) {
        #pragma unroll
        for (int t = 0; t < 16; ++t) {
            const int kt = t * 16 + 2 * lj;
            frag[t*4+0] = *(const uint32_t*)&Ks[(rt * 16 + lr4) * NT + kt];
            frag[t*4+1] = *(const uint32_t*)&Ks[(rt * 16 + 8 + lr4) * NT + kt];
            frag[t*4+2] = *(const uint32_t*)&Ks[(rt * 16 + lr4) * NT + kt + 8];
            frag[t*4+3] = *(const uint32_t*)&Ks[(rt * 16 + 8 + lr4) * NT + kt + 8];
        }
    } else {
        #pragma unroll
        for (int j = 0; j < 4; ++j) {
            const int col = (wc * 4 + j) * 8 + lr4;
            #pragma unroll
            for (int t = 0; t < 8; ++t) {
                const int k0 = t * 16 + 2 * lj;
                frag[(j*8+t)*2+0] = h2_as_u32(Ks[(size_t)k0 * NT + col],
                                              Ks[(size_t)(k0 + 1) * NT + col]);
                frag[(j*8+t)*2+1] = h2_as_u32(Ks[(size_t)(k0 + 8) * NT + col],
                                              Ks[(size_t)(k0 + 9) * NT + col]);
            }
        }
    }

    for (int it = 0; it < NITER; ++it) {
        __syncthreads();   // vh(it) visible to row warps
        if (roww) {
            float cc[4][4] = {};
            #pragma unroll
            for (int t = 0; t < 16; t += 4) {
                #pragma unroll
                for (int q = 0; q < 4; ++q) {
                    const int kt = (t + q) * 16 + 2 * lj;
                    mma16816f(cc[q],
                              frag[(t+q)*4+0], frag[(t+q)*4+1],
                              frag[(t+q)*4+2], frag[(t+q)*4+3],
                              *(const uint32_t*)&vh[kt],
                              *(const uint32_t*)&vh[kt + 8]);
                }
            }
            if (lj == 0) {
                const float s0 = (cc[0][0] + cc[1][0]) + (cc[2][0] + cc[3][0]);
                const float s2 = (cc[0][2] + cc[1][2]) + (cc[2][2] + cc[3][2]);
                const float u0 = __fdividef(MUC, s0);
                const float u2 = __fdividef(MUC, s2);
                const int i0 = rt * 16 + lr4;
                u[i0] = u0;      uh[i0] = __float2half_rn(u0 * 64.0f);
                u[i0 + 8] = u2;  uh[i0 + 8] = __float2half_rn(u2 * 64.0f);
            }
        }
        __syncthreads();   // uh visible to col warps
        if (!roww) {
            const int buf = it & 1;
            float cc[4][4] = {};
            #pragma unroll
            for (int t = 0; t < 8; ++t) {
                const int k0 = t * 16 + 2 * lj;
                const uint32_t a0 = *(const uint32_t*)&uh[k0];
                const uint32_t a2 = *(const uint32_t*)&uh[k0 + 8];
                #pragma unroll
                for (int j = 0; j < 4; ++j)
                    mma16816f(cc[j], a0, a0, a2, a2,
                              frag[(j*8+t)*2+0], frag[(j*8+t)*2+1]);
            }
            if (lane < 4) {
                #pragma unroll
                for (int j = 0; j < 4; ++j) {
                    const int idx = (wc * 4 + j) * 8 + 2 * lane;
                    unsigned long long pk;
                    asm("mov.b64 %0, {%1, %2};" : "=l"(pk) : "f"(cc[j][0]), "f"(cc[j][1]));
                    asm volatile("st.shared::cluster.b64 [%0], %1;"
                                 :: "r"(recv_peer + (uint32_t)((buf * NT + idx) * 4)), "l"(pk)
                                 : "memory");
                }
                asm volatile("mbarrier.arrive.release.cluster.shared::cluster.b64 _, [%0];"
                             :: "r"(mbar_peer) : "memory");
                uint32_t done;
                asm volatile("{ .reg .pred p; "
                             "mbarrier.try_wait.parity.acquire.cluster.shared::cta.b64 p, [%1], %2; "
                             "selp.b32 %0, 1, 0, p; }"
                             : "=r"(done) : "r"(mbar_local), "r"((uint32_t)buf) : "memory");
                while (!done) {
                    asm volatile("{ .reg .pred p; "
                                 "mbarrier.try_wait.parity.acquire.cluster.shared::cta.b64 p, [%1], %2, 0x989680; "
                                 "selp.b32 %0, 1, 0, p; }"
                                 : "=r"(done) : "r"(mbar_local), "r"((uint32_t)buf) : "memory");
                }
                #pragma unroll
                for (int j = 0; j < 4; ++j) {
                    const int idx = (wc * 4 + j) * 8 + 2 * lane;
                    const float p0 = recv[buf * NT + idx];
                    const float p1 = recv[buf * NT + idx + 1];
                    const float s0 = rank == 0 ? (cc[j][0] + p0) : (p0 + cc[j][0]);
                    const float s1 = rank == 0 ? (cc[j][1] + p1) : (p1 + cc[j][1]);
                    const float nv0 = __fdividef(0.25f, s0);   // MUC*64 (uh scale cancels)
                    const float nv1 = __fdividef(0.25f, s1);
                    v[idx] = nv0;     vh[idx] = __float2half_rn(nv0);
                    v[idx + 1] = nv1; vh[idx + 1] = __float2half_rn(nv1);
                }
            }
        }
    }
    __syncthreads();   // final u, v visible to all

    // ---- transport loss over my 128 rows (warp w -> rows 8w..8w+7)
    float vl[8];
    {
        const float4 v0 = *(const float4*)&v[lane * 8];
        const float4 v1 = *(const float4*)&v[lane * 8 + 4];
        vl[0]=v0.x; vl[1]=v0.y; vl[2]=v0.z; vl[3]=v0.w;
        vl[4]=v1.x; vl[5]=v1.y; vl[6]=v1.z; vl[7]=v1.w;
    }
    float acc = 0.0f;
    #pragma unroll
    for (int r = 0; r < 8; ++r) {
        const int i = w * 8 + r;
        const float ui = u[i];
        const uint4 kw = *(const uint4*)(Ks + (size_t)i * NT + lane * 8);
        float kf[8];
        {
            float2 f;
            f = __half22float2(*(const __half2*)&kw.x); kf[0]=f.x; kf[1]=f.y;
            f = __half22float2(*(const __half2*)&kw.y); kf[2]=f.x; kf[3]=f.y;
            f = __half22float2(*(const __half2*)&kw.z); kf[4]=f.x; kf[5]=f.y;
            f = __half22float2(*(const __half2*)&kw.w); kf[6]=f.x; kf[7]=f.y;
        }
        #pragma unroll
        for (int q = 0; q < 8; ++q) {
            const float k = kf[q];
            if (k > 0.0f) {
                const float cost = (SHIFTF - __log2f(k)) * INV_K2;  // == 1 - dot
                acc = fmaf(ui * k * vl[q], cost, acc);
            }
        }
    }
    #pragma unroll
    for (int o = 16; o; o >>= 1) acc += __shfl_xor_sync(0xffffffffu, acc, o);
    if (lane == 0) red[w] = acc;
    __syncthreads();
    if (w == 0) {
        float s = (lane < 16) ? red[lane] : 0.0f;
        #pragma unroll
        for (int o = 16; o; o >>= 1) s += __shfl_xor_sync(0xffffffffu, s, o);
        if (lane == 0) {
            g_part[blockIdx.x] = s;
            __threadfence();
            if (atomicAdd(&g_ctr, 1u) == 2 * NB - 1) {   // last CTA: deterministic mean
                __threadfence();
                float tot = 0.0f;
                #pragma unroll
                for (int i = 0; i < 2 * NB; ++i) tot += __ldcg(&g_part[i]);
                out[0] = tot * (1.0f / NB);
            }
        }
    }
    asm volatile("barrier.cluster.arrive.aligned;" ::: "memory");
    asm volatile("barrier.cluster.wait.aligned;" ::: "memory");
}

// ============================================================================
extern "C" void kernel_launch(void* const* d_in, const int* in_sizes, int n_in,
                              void* d_out, int out_size)
{
    const float* pred = (const float*)d_in[0];
    const float* tgt  = (const float*)d_in[1];
    float* out = (float*)d_out;

    gather_kernel<<<dim3(NB, 2, 8), 256>>>(pred, tgt);

    cudaFuncSetAttribute(cost_kernel, cudaFuncAttributeMaxDynamicSharedMemorySize, COST_SMEM);
    cost_kernel<<<dim3(2, NB), 256, COST_SMEM>>>();

    cudaFuncSetAttribute(sinkhorn_kernel, cudaFuncAttributeMaxDynamicSharedMemorySize, SK_SMEM);
    sinkhorn_kernel<<<2 * NB, 512, SK_SMEM>>>(out);
}

// round 14
// speedup vs baseline: 1.4579x; 1.4579x over previous
#include <cuda_runtime.h>
#include <cuda_fp16.h>
#include <cuda_bf16.h>
#include <cstdint>

// ---------------- problem constants ----------------
#define NB   64
#define NT   256
#define NC   256
#define HW   4096
#define NITER 30

#define K2C     28.853900817779268f   // log2(e)/eps
#define INV_K2  0.03465735902799727f  // eps*ln2
#define SHIFTF  26.0f
#define MUC     (1.0f/256.0f)

// ---------------- scratch ----------------
__device__ __align__(16) __nv_bfloat16 g_tok[(size_t)2 * NB * NT * NC];  // [z][b][i][c]
__device__ __align__(16) __half        g_K[(size_t)NB * NT * NT];
__device__ float    g_part[2 * NB];
__device__ unsigned g_ctr;

__device__ __forceinline__ uint32_t smem_u32(const void* p) {
    uint32_t a;
    asm("{ .reg .u64 t; cvta.to.shared.u64 t, %1; cvt.u32.u64 %0, t; }" : "=r"(a) : "l"(p));
    return a;
}
__device__ __forceinline__ uint32_t h2_as_u32(__half lo, __half hi) {
    union { __half2 h; uint32_t u; } c;
    c.h = __halves2half2(lo, hi);
    return c.u;
}

// ============================================================================
// Kernel 1: FUSED streaming sampler + l2norm + transpose (round-12 exact).
// grid (64, 2), 1024 threads. CTA reads its whole (b,z) plane (4MB) coalesced.
// ============================================================================
#define TSTR 264
#define GNF_SMEM (256 * TSTR * 2 + 4096 + 1024)

__global__ __launch_bounds__(1024, 1) void gather_norm_fused(
    const float* __restrict__ pred, const float* __restrict__ tgt)
{
    extern __shared__ unsigned char sm[];
    __nv_bfloat16* T = (__nv_bfloat16*)sm;               // [256 c][264] swizzled
    float* pss = (float*)(sm + 256 * TSTR * 2);          // [4][256]
    float* inv = (float*)(sm + 256 * TSTR * 2 + 4096);   // [256]

    const int b = blockIdx.x, z = blockIdx.y;
    if (threadIdx.x == 0 && (b | z) == 0) g_ctr = 0u;
    const int tid = threadIdx.x;
    const float DELTA = 4095.0f / 255.0f;

    const float4* __restrict__ src =
        (const float4*)((z ? tgt : pred) + (size_t)b * NC * HW);

    const int p4 = tid * 4;
    const int cand = (int)(__fdividef((float)(p4 + 2), DELTA));
    int hit_i = -1, hit_off = 0;
    #pragma unroll
    for (int d = -1; d <= 1; ++d) {
        const int i = cand + d;
        if (i >= 0 && i < 256) {
            const int s = (int)(__fmul_rn((float)i, DELTA));  // exact ref trunc
            if (s >= p4 && s < p4 + 4) { hit_i = i; hit_off = s - p4; }
        }
    }
    const int ibs = (hit_i >= 0) ? (hit_i >> 3) : 0;
    const int ios = (hit_i >= 0) ? (hit_i & 7) : 0;

    #pragma unroll 2
    for (int c4 = 0; c4 < NC; c4 += 4) {
        float4 f[4];
        #pragma unroll
        for (int q = 0; q < 4; ++q) f[q] = __ldcs(&src[(size_t)(c4 + q) * 1024 + tid]);
        if (hit_i >= 0) {
            #pragma unroll
            for (int q = 0; q < 4; ++q) {
                const int c = c4 + q;
                const float* fv = (const float*)&f[q];
                T[c * TSTR + ((ibs ^ ((c >> 3) & 7)) << 3) + ios] =
                    __float2bfloat16(fv[hit_off]);
            }
        }
    }
    __syncthreads();

    {
        const int i = tid & 255, part = tid >> 8;
        const int ib = i >> 3, io = i & 7;
        float ss = 0.0f;
        #pragma unroll 8
        for (int cc = 0; cc < 64; ++cc) {
            const int c = part * 64 + cc;
            const float x = __bfloat162float(
                T[c * TSTR + ((ib ^ ((c >> 3) & 7)) << 3) + io]);
            ss = fmaf(x, x, ss);
        }
        pss[part * 256 + i] = ss;
    }
    __syncthreads();
    if (tid < 256) {
        const float ss = pss[tid] + pss[256 + tid] + pss[512 + tid] + pss[768 + tid];
        inv[tid] = __fdividef(1.0f, fmaxf(sqrtf(ss), 1e-12f));
    }
    __syncthreads();

    uint4* __restrict__ dst = (uint4*)(g_tok + ((size_t)z * NB + b) * NT * NC);
    #pragma unroll
    for (int k = 0; k < 8; ++k) {
        const int idx = tid + k * 1024;
        const int i = idx >> 5, c0 = (idx & 31) * 8;
        const float sc = inv[i];
        const int ib = i >> 3, io = i & 7;
        union { uint4 u; __nv_bfloat16 h[8]; } o;
        #pragma unroll
        for (int j = 0; j < 8; ++j) {
            const int c = c0 + j;
            const float x = __bfloat162float(
                T[c * TSTR + ((ib ^ ((c >> 3) & 7)) << 3) + io]);
            o.h[j] = __float2bfloat16(x * sc);
        }
        dst[idx] = o.u;
    }
}

// ============================================================================
// Kernel 2: cost GEMM via mma.sync bf16 (round-12 exact).
// ============================================================================
#define SPAD 264
#define COST_SMEM ((128 + 256) * SPAD * 2)

__device__ __forceinline__ void mma16816bf(float* c, uint32_t a0, uint32_t a1,
                                           uint32_t a2, uint32_t a3,
                                           uint32_t b0, uint32_t b1) {
    asm volatile(
        "mma.sync.aligned.m16n8k16.row.col.f32.bf16.bf16.f32 "
        "{%0,%1,%2,%3}, {%4,%5,%6,%7}, {%8,%9}, {%0,%1,%2,%3};"
        : "+f"(c[0]), "+f"(c[1]), "+f"(c[2]), "+f"(c[3])
        : "r"(a0), "r"(a1), "r"(a2), "r"(a3), "r"(b0), "r"(b1));
}

__global__ __launch_bounds__(256, 1) void cost_kernel()
{
    extern __shared__ char smem[];
    __nv_bfloat16* As = (__nv_bfloat16*)smem;
    __nv_bfloat16* Bs = (__nv_bfloat16*)(smem + 128 * SPAD * 2);

    const int mh = blockIdx.x;
    const int b  = blockIdx.y;
    const int tid = threadIdx.x, w = tid >> 5, lane = tid & 31;

    const uint4* __restrict__ Ag =
        (const uint4*)(g_tok + ((size_t)b * NT + (size_t)mh * 128) * NC);
    #pragma unroll
    for (int it = 0; it < 16; ++it) {
        const int idx = tid + it * 256;
        *(uint4*)(As + (idx >> 5) * SPAD + (idx & 31) * 8) = Ag[idx];
    }
    const uint4* __restrict__ Bg = (const uint4*)(g_tok + ((size_t)(NB + b)) * NT * NC);
    #pragma unroll
    for (int it = 0; it < 32; ++it) {
        const int idx = tid + it * 256;
        *(uint4*)(Bs + (idx >> 5) * SPAD + (idx & 31) * 8) = Bg[idx];
    }
    __syncthreads();

    const int r0 = w * 16;
    const int lr = lane >> 2;
    const int lj = lane & 3;

    const __nv_bfloat16* A0 = As + (r0 + lr) * SPAD + lj * 2;
    const __nv_bfloat16* A8 = A0 + 8 * SPAD;
    const __nv_bfloat16* B0 = Bs + lr * SPAD + lj * 2;

    __half* __restrict__ K0 = g_K + ((size_t)b * NT + (size_t)(mh * 128 + r0 + lr)) * NT;
    __half* __restrict__ K8 = K0 + 8 * NT;

    #pragma unroll
    for (int h = 0; h < 2; ++h) {
        float c[16][4];
        #pragma unroll
        for (int nt = 0; nt < 16; ++nt)
            c[nt][0] = c[nt][1] = c[nt][2] = c[nt][3] = 0.0f;

        #pragma unroll
        for (int kc = 0; kc < 16; ++kc) {
            const int ko = kc * 16;
            const uint32_t a0 = *(const uint32_t*)(A0 + ko);
            const uint32_t a1 = *(const uint32_t*)(A8 + ko);
            const uint32_t a2 = *(const uint32_t*)(A0 + ko + 8);
            const uint32_t a3 = *(const uint32_t*)(A8 + ko + 8);
            #pragma unroll
            for (int nt = 0; nt < 16; ++nt) {
                const __nv_bfloat16* bp = B0 + (h * 128 + nt * 8) * SPAD + ko;
                mma16816bf(c[nt], a0, a1, a2, a3,
                           *(const uint32_t*)bp, *(const uint32_t*)(bp + 8));
            }
        }

        #pragma unroll
        for (int nt = 0; nt < 16; ++nt) {
            const int col = h * 128 + nt * 8 + lj * 2;
            *(__half2*)(K0 + col) = __halves2half2(
                __float2half_rn(exp2f(fmaf(c[nt][0] - 1.0f, K2C, SHIFTF))),
                __float2half_rn(exp2f(fmaf(c[nt][1] - 1.0f, K2C, SHIFTF))));
            *(__half2*)(K8 + col) = __halves2half2(
                __float2half_rn(exp2f(fmaf(c[nt][2] - 1.0f, K2C, SHIFTF))),
                __float2half_rn(exp2f(fmaf(c[nt][3] - 1.0f, K2C, SHIFTF))));
        }
    }
}

// ============================================================================
// Kernel 3: Sinkhorn, warp-specialized.  NEW: v-pass computes colsums as
// K^T * u (A = K^T fragments, full 16-wide M = columns), halving v-phase
// MMA count 256 -> 128 per CTA.  Row pass unchanged.
// ============================================================================
#define SK_KS    0
#define SK_RECV  65536                 // [2][256] f32 peer-pushed colsums
#define SK_V     (SK_RECV + 2048)      // [256] f32
#define SK_U     (SK_V + 1024)         // [128] f32
#define SK_UH    (SK_U + 512)          // [128] f16 (scaled x64)
#define SK_VH    (SK_UH + 256)         // [256] f16
#define SK_RED   (SK_VH + 512)         // [16] f32 (pad)
#define SK_MBAR  (SK_RED + 128)
#define SK_SMEM  (SK_MBAR + 16)

__device__ __forceinline__ void mma16816f(float* c, uint32_t a0, uint32_t a1,
                                          uint32_t a2, uint32_t a3,
                                          uint32_t b0, uint32_t b1) {
    asm volatile(
        "mma.sync.aligned.m16n8k16.row.col.f32.f16.f16.f32 "
        "{%0,%1,%2,%3}, {%4,%5,%6,%7}, {%8,%9}, {%0,%1,%2,%3};"
        : "+f"(c[0]), "+f"(c[1]), "+f"(c[2]), "+f"(c[3])
        : "r"(a0), "r"(a1), "r"(a2), "r"(a3), "r"(b0), "r"(b1));
}

__global__ __launch_bounds__(512, 1) __cluster_dims__(2, 1, 1)
void sinkhorn_kernel(float* __restrict__ out)
{
    extern __shared__ unsigned char sm[];
    __half* Ks   = (__half*)(sm + SK_KS);      // [128][256] local rows
    float*  recv = (float*)(sm + SK_RECV);
    float*  v    = (float*)(sm + SK_V);
    float*  u    = (float*)(sm + SK_U);
    __half* uh   = (__half*)(sm + SK_UH);
    __half* vh   = (__half*)(sm + SK_VH);
    float*  red  = (float*)(sm + SK_RED);

    const int rank = blockIdx.x & 1;
    const int b    = blockIdx.x >> 1;
    const int tid  = threadIdx.x;
    const int w    = tid >> 5, lane = tid & 31;
    const int lr4  = lane >> 2, lj = lane & 3;

    const uint32_t mbar_local = smem_u32(sm + SK_MBAR);
    uint32_t recv_peer, mbar_peer;
    {
        const uint32_t recv_local = smem_u32(recv);
        asm("mapa.shared::cluster.u32 %0, %1, %2;" : "=r"(recv_peer)
            : "r"(recv_local), "r"(rank ^ 1));
        asm("mapa.shared::cluster.u32 %0, %1, %2;" : "=r"(mbar_peer)
            : "r"(mbar_local), "r"(rank ^ 1));
    }

    if (tid == 0) {
        asm volatile("mbarrier.init.shared.b64 [%0], %1;"
                     :: "r"(mbar_local), "r"(64u) : "memory");
    }

    {   // load my 128 rows of K' (64 KB)
        const uint4* gk = (const uint4*)(g_K + ((size_t)b * NT + (size_t)rank * 128) * NT);
        uint4* sk = (uint4*)Ks;
        #pragma unroll
        for (int q = 0; q < 8; ++q) sk[tid + q * 512] = gk[tid + q * 512];
    }
    if (tid < NT) { v[tid] = 1.0f; vh[tid] = __float2half_rn(1.0f); }
    __syncthreads();

    // cluster sync once: peer mbarrier init visible before any remote push
    asm volatile("barrier.cluster.arrive.aligned;" ::: "memory");
    asm volatile("barrier.cluster.wait.aligned;" ::: "memory");

    // ---- role-shared fragment storage (disjoint indexing per role) ----
    uint32_t frag[64];
    const bool roww = (w < 8);
    const int rt = w;           // row warp: rows rt*16..+15
    const int wc = w - 8;       // col warp: m-tiles (cols) 2wc, 2wc+1

    if (roww) {
        // row fragments: A = K (row-major), 16 k-tiles
        #pragma unroll
        for (int t = 0; t < 16; ++t) {
            const int kt = t * 16 + 2 * lj;
            frag[t*4+0] = *(const uint32_t*)&Ks[(rt * 16 + lr4) * NT + kt];
            frag[t*4+1] = *(const uint32_t*)&Ks[(rt * 16 + 8 + lr4) * NT + kt];
            frag[t*4+2] = *(const uint32_t*)&Ks[(rt * 16 + lr4) * NT + kt + 8];
            frag[t*4+3] = *(const uint32_t*)&Ks[(rt * 16 + 8 + lr4) * NT + kt + 8];
        }
    } else {
        // col fragments: A = K^T (m = columns of K, k = local rows), 2 m-tiles x 8 k-tiles
        #pragma unroll
        for (int mt = 0; mt < 2; ++mt) {
            const int j0 = (2 * wc + mt) * 16 + lr4;   // column for a0/a2
            const int j1 = j0 + 8;                      // column for a1/a3
            #pragma unroll
            for (int t = 0; t < 8; ++t) {
                const int k0 = t * 16 + 2 * lj;
                frag[(mt*8+t)*4+0] = h2_as_u32(Ks[(size_t)k0 * NT + j0],
                                               Ks[(size_t)(k0 + 1) * NT + j0]);
                frag[(mt*8+t)*4+1] = h2_as_u32(Ks[(size_t)k0 * NT + j1],
                                               Ks[(size_t)(k0 + 1) * NT + j1]);
                frag[(mt*8+t)*4+2] = h2_as_u32(Ks[(size_t)(k0 + 8) * NT + j0],
                                               Ks[(size_t)(k0 + 9) * NT + j0]);
                frag[(mt*8+t)*4+3] = h2_as_u32(Ks[(size_t)(k0 + 8) * NT + j1],
                                               Ks[(size_t)(k0 + 9) * NT + j1]);
            }
        }
    }

    for (int it = 0; it < NITER; ++it) {
        __syncthreads();   // vh(it) visible to row warps
        if (roww) {
            float cc[4][4] = {};
            #pragma unroll
            for (int t = 0; t < 16; t += 4) {
                #pragma unroll
                for (int q = 0; q < 4; ++q) {
                    const int kt = (t + q) * 16 + 2 * lj;
                    mma16816f(cc[q],
                              frag[(t+q)*4+0], frag[(t+q)*4+1],
                              frag[(t+q)*4+2], frag[(t+q)*4+3],
                              *(const uint32_t*)&vh[kt],
                              *(const uint32_t*)&vh[kt + 8]);
                }
            }
            if (lj == 0) {
                const float s0 = (cc[0][0] + cc[1][0]) + (cc[2][0] + cc[3][0]);
                const float s2 = (cc[0][2] + cc[1][2]) + (cc[2][2] + cc[3][2]);
                const float u0 = __fdividef(MUC, s0);
                const float u2 = __fdividef(MUC, s2);
                const int i0 = rt * 16 + lr4;
                u[i0] = u0;      uh[i0] = __float2half_rn(u0 * 64.0f);
                u[i0 + 8] = u2;  uh[i0 + 8] = __float2half_rn(u2 * 64.0f);
            }
        }
        __syncthreads();   // uh visible to col warps
        if (!roww) {
            const int buf = it & 1;
            // ---- v-pass: colsums via K^T * u.  2 m-tiles, chains of depth 8.
            float cc[2][4] = {};
            #pragma unroll
            for (int t = 0; t < 8; ++t) {
                const int k0 = t * 16 + 2 * lj;
                const uint32_t b0 = *(const uint32_t*)&uh[k0];
                const uint32_t b1 = *(const uint32_t*)&uh[k0 + 8];
                #pragma unroll
                for (int mt = 0; mt < 2; ++mt)
                    mma16816f(cc[mt],
                              frag[(mt*8+t)*4+0], frag[(mt*8+t)*4+1],
                              frag[(mt*8+t)*4+2], frag[(mt*8+t)*4+3],
                              b0, b1);
            }
            if (lj == 0) {   // 8 writer lanes per warp, 2 cols per m-tile each
                #pragma unroll
                for (int mt = 0; mt < 2; ++mt) {
                    const int j0 = (2 * wc + mt) * 16 + lr4;
                    asm volatile("st.shared::cluster.b32 [%0], %1;"
                                 :: "r"(recv_peer + (uint32_t)((buf * NT + j0) * 4)),
                                    "f"(cc[mt][0]) : "memory");
                    asm volatile("st.shared::cluster.b32 [%0], %1;"
                                 :: "r"(recv_peer + (uint32_t)((buf * NT + j0 + 8) * 4)),
                                    "f"(cc[mt][2]) : "memory");
                }
                asm volatile("mbarrier.arrive.release.cluster.shared::cluster.b64 _, [%0];"
                             :: "r"(mbar_peer) : "memory");
                uint32_t done;
                asm volatile("{ .reg .pred p; "
                             "mbarrier.try_wait.parity.acquire.cluster.shared::cta.b64 p, [%1], %2; "
                             "selp.b32 %0, 1, 0, p; }"
                             : "=r"(done) : "r"(mbar_local), "r"((uint32_t)buf) : "memory");
                while (!done) {
                    asm volatile("{ .reg .pred p; "
                                 "mbarrier.try_wait.parity.acquire.cluster.shared::cta.b64 p, [%1], %2, 0x989680; "
                                 "selp.b32 %0, 1, 0, p; }"
                                 : "=r"(done) : "r"(mbar_local), "r"((uint32_t)buf) : "memory");
                }
                #pragma unroll
                for (int mt = 0; mt < 2; ++mt) {
                    const int j0 = (2 * wc + mt) * 16 + lr4;
                    const float p0 = recv[buf * NT + j0];
                    const float p1 = recv[buf * NT + j0 + 8];
                    const float s0 = rank == 0 ? (cc[mt][0] + p0) : (p0 + cc[mt][0]);
                    const float s1 = rank == 0 ? (cc[mt][2] + p1) : (p1 + cc[mt][2]);
                    const float nv0 = __fdividef(0.25f, s0);   // MUC*64 (uh scale cancels)
                    const float nv1 = __fdividef(0.25f, s1);
                    v[j0] = nv0;     vh[j0] = __float2half_rn(nv0);
                    v[j0 + 8] = nv1; vh[j0 + 8] = __float2half_rn(nv1);
                }
            }
        }
    }
    __syncthreads();   // final u, v visible to all

    // ---- transport loss over my 128 rows (warp w -> rows 8w..8w+7)
    float vl[8];
    {
        const float4 v0 = *(const float4*)&v[lane * 8];
        const float4 v1 = *(const float4*)&v[lane * 8 + 4];
        vl[0]=v0.x; vl[1]=v0.y; vl[2]=v0.z; vl[3]=v0.w;
        vl[4]=v1.x; vl[5]=v1.y; vl[6]=v1.z; vl[7]=v1.w;
    }
    float acc = 0.0f;
    #pragma unroll
    for (int r = 0; r < 8; ++r) {
        const int i = w * 8 + r;
        const float ui = u[i];
        const uint4 kw = *(const uint4*)(Ks + (size_t)i * NT + lane * 8);
        float kf[8];
        {
            float2 f;
            f = __half22float2(*(const __half2*)&kw.x); kf[0]=f.x; kf[1]=f.y;
            f = __half22float2(*(const __half2*)&kw.y); kf[2]=f.x; kf[3]=f.y;
            f = __half22float2(*(const __half2*)&kw.z); kf[4]=f.x; kf[5]=f.y;
            f = __half22float2(*(const __half2*)&kw.w); kf[6]=f.x; kf[7]=f.y;
        }
        #pragma unroll
        for (int q = 0; q < 8; ++q) {
            const float k = kf[q];
            if (k > 0.0f) {
                const float cost = (SHIFTF - __log2f(k)) * INV_K2;  // == 1 - dot
                acc = fmaf(ui * k * vl[q], cost, acc);
            }
        }
    }
    #pragma unroll
    for (int o = 16; o; o >>= 1) acc += __shfl_xor_sync(0xffffffffu, acc, o);
    if (lane == 0) red[w] = acc;
    __syncthreads();
    if (w == 0) {
        float s = (lane < 16) ? red[lane] : 0.0f;
        #pragma unroll
        for (int o = 16; o; o >>= 1) s += __shfl_xor_sync(0xffffffffu, s, o);
        if (lane == 0) {
            g_part[blockIdx.x] = s;
            __threadfence();
            if (atomicAdd(&g_ctr, 1u) == 2 * NB - 1) {   // last CTA: deterministic mean
                __threadfence();
                float tot = 0.0f;
                #pragma unroll
                for (int i = 0; i < 2 * NB; ++i) tot += __ldcg(&g_part[i]);
                out[0] = tot * (1.0f / NB);
            }
        }
    }
    // no CTA may exit while peer pushes could still target its smem
    asm volatile("barrier.cluster.arrive.aligned;" ::: "memory");
    asm volatile("barrier.cluster.wait.aligned;" ::: "memory");
}

// ============================================================================
extern "C" void kernel_launch(void* const* d_in, const int* in_sizes, int n_in,
                              void* d_out, int out_size)
{
    const float* pred = (const float*)d_in[0];
    const float* tgt  = (const float*)d_in[1];
    float* out = (float*)d_out;

    cudaFuncSetAttribute(gather_norm_fused, cudaFuncAttributeMaxDynamicSharedMemorySize, GNF_SMEM);
    gather_norm_fused<<<dim3(NB, 2), 1024, GNF_SMEM>>>(pred, tgt);

    cudaFuncSetAttribute(cost_kernel, cudaFuncAttributeMaxDynamicSharedMemorySize, COST_SMEM);
    cost_kernel<<<dim3(2, NB), 256, COST_SMEM>>>();

    cudaFuncSetAttribute(sinkhorn_kernel, cudaFuncAttributeMaxDynamicSharedMemorySize, SK_SMEM);
    sinkhorn_kernel<<<2 * NB, 512, SK_SMEM>>>(out);
}